// round 1
// baseline (speedup 1.0000x reference)
#include <cuda_runtime.h>
#include <math.h>

#define B_  2
#define S_  2048
#define D_  1024
#define H_  16
#define HD_ 64
#define M_  (B_ * S_)    // 4096
#define N3_ (3 * D_)     // 3072

// Scratch for Q/K/V in (b*H+h, s, e) layout. 16MB each.
__device__ float g_Q[(size_t)M_ * D_];
__device__ float g_K[(size_t)M_ * D_];
__device__ float g_V[(size_t)M_ * D_];

// ---------------------------------------------------------------------------
// Kernel 1: fused QKV projection.
// C[4096,3072] = A[4096,1024] @ W[1024,3072], epilogue scatters to g_Q/g_K/g_V
// in (b,h,s,e) layout, applying q bias+scale and v bias.
// Tiling: BM=128, BN=128, BK=8, 256 threads, 8x8 micro-tile.
// ---------------------------------------------------------------------------
__global__ __launch_bounds__(256) void qkv_gemm_kernel(
    const float* __restrict__ A, const float* __restrict__ W,
    const float* __restrict__ qb, const float* __restrict__ vb)
{
    __shared__ float As[8][128];
    __shared__ float Bs[8][128];

    const int tid = threadIdx.x;
    const int bm  = blockIdx.y * 128;
    const int bn  = blockIdx.x * 128;
    const int ty  = tid >> 4;      // 0..15 -> row group
    const int tx  = tid & 15;      // 0..15 -> col group

    // load mapping
    const int arow = tid >> 1;           // 0..127
    const int acol = (tid & 1) << 2;     // 0 or 4
    const int brow = tid >> 5;           // 0..7
    const int bcol = (tid & 31) << 2;    // 0..124

    const float* Ap = A + (size_t)(bm + arow) * D_ + acol;
    const float* Wp = W + (size_t)brow * N3_ + bn + bcol;

    float acc[8][8];
    #pragma unroll
    for (int i = 0; i < 8; i++)
        #pragma unroll
        for (int j = 0; j < 8; j++) acc[i][j] = 0.f;

    for (int k0 = 0; k0 < D_; k0 += 8) {
        float4 av = *(const float4*)(Ap + k0);
        float4 wv = *(const float4*)(Wp + (size_t)k0 * N3_);
        __syncthreads();   // previous iteration's compute done reading smem
        As[acol + 0][arow] = av.x;
        As[acol + 1][arow] = av.y;
        As[acol + 2][arow] = av.z;
        As[acol + 3][arow] = av.w;
        *(float4*)&Bs[brow][bcol] = wv;
        __syncthreads();

        #pragma unroll
        for (int k = 0; k < 8; k++) {
            float a[8], b[8];
            *(float4*)&a[0] = *(const float4*)&As[k][ty * 8];
            *(float4*)&a[4] = *(const float4*)&As[k][ty * 8 + 4];
            *(float4*)&b[0] = *(const float4*)&Bs[k][tx * 8];
            *(float4*)&b[4] = *(const float4*)&Bs[k][tx * 8 + 4];
            #pragma unroll
            for (int i = 0; i < 8; i++)
                #pragma unroll
                for (int j = 0; j < 8; j++)
                    acc[i][j] = fmaf(a[i], b[j], acc[i][j]);
        }
    }

    // Epilogue: scatter into (b*H+h, s, e) layout with bias/scale.
    #pragma unroll
    for (int i = 0; i < 8; i++) {
        int mrow = bm + ty * 8 + i;
        int b = mrow >> 11;             // /2048
        int s = mrow & (S_ - 1);
        #pragma unroll
        for (int j = 0; j < 8; j++) {
            int n = bn + tx * 8 + j;
            int which = n >> 10;        // 0=q 1=k 2=v (constant per block)
            int d = n & (D_ - 1);
            int h = d >> 6;
            int e = d & 63;
            size_t idx = ((size_t)(b * H_ + h) * S_ + s) * HD_ + e;
            float v = acc[i][j];
            if (which == 0)      g_Q[idx] = (v + qb[d]) * 0.125f;  // 1/sqrt(64)
            else if (which == 1) g_K[idx] = v;
            else                 g_V[idx] = v + vb[d];
        }
    }
}

// ---------------------------------------------------------------------------
// Kernel 2: flash attention, fp32, online softmax.
// Grid: (S/64 query tiles, B*H). Block: 256 threads.
// 4 threads per query row (r = tid/4, tx = tid%4).
// Score columns interleaved c = 4j+tx (conflict-free smem reads).
// P row exchanged via width-4 shuffles (no smem P buffer).
// K and V share one smem tile (keeps static smem at 34.8KB < 48KB).
// ---------------------------------------------------------------------------
__global__ __launch_bounds__(256) void attn_kernel(float* __restrict__ out)
{
    __shared__ float Qs[64][68];
    __shared__ float KVs[64][68];

    const int tid = threadIdx.x;
    const int r   = tid >> 2;     // query row 0..63
    const int tx  = tid & 3;      // 0..3
    const int tx8 = tx * 8;
    const int bh  = blockIdx.y;   // b*16 + h
    const int qt  = blockIdx.x;   // query tile 0..31

    const float* Qb = g_Q + ((size_t)bh * S_ + qt * 64) * HD_;
    const float* Kb = g_K + (size_t)bh * S_ * HD_;
    const float* Vb = g_V + (size_t)bh * S_ * HD_;

    // Load Q tile (64x64 floats, 4 float4 per thread)
    #pragma unroll
    for (int i = 0; i < 4; i++) {
        int idx = tid + i * 256;
        int rr = idx >> 4;
        int cc = (idx & 15) << 2;
        *(float4*)&Qs[rr][cc] = *(const float4*)(Qb + rr * HD_ + cc);
    }

    float mrow = -INFINITY, lrow = 0.f;
    float o[16];
    #pragma unroll
    for (int i = 0; i < 16; i++) o[i] = 0.f;

    for (int kt = 0; kt < S_ / 64; kt++) {
        // ---- load K tile ----
        const float* Kt = Kb + (size_t)kt * 64 * HD_;
        __syncthreads();   // previous PV done reading KVs
        #pragma unroll
        for (int i = 0; i < 4; i++) {
            int idx = tid + i * 256;
            int rr = idx >> 4;
            int cc = (idx & 15) << 2;
            *(float4*)&KVs[rr][cc] = *(const float4*)(Kt + rr * HD_ + cc);
        }
        __syncthreads();

        // ---- scores: s[j] = Qs[r] . K[4j+tx] ----
        float s[16];
        #pragma unroll
        for (int j = 0; j < 16; j++) s[j] = 0.f;
        #pragma unroll
        for (int k = 0; k < 64; k += 4) {
            float4 qv = *(const float4*)&Qs[r][k];
            #pragma unroll
            for (int j = 0; j < 16; j++) {
                float4 kv = *(const float4*)&KVs[j * 4 + tx][k];
                s[j] = fmaf(qv.x, kv.x, s[j]);
                s[j] = fmaf(qv.y, kv.y, s[j]);
                s[j] = fmaf(qv.z, kv.z, s[j]);
                s[j] = fmaf(qv.w, kv.w, s[j]);
            }
        }

        // ---- online softmax (row owned by 4 consecutive lanes) ----
        float mx = s[0];
        #pragma unroll
        for (int j = 1; j < 16; j++) mx = fmaxf(mx, s[j]);
        mx = fmaxf(mx, __shfl_xor_sync(0xffffffffu, mx, 1));
        mx = fmaxf(mx, __shfl_xor_sync(0xffffffffu, mx, 2));
        float mnew = fmaxf(mrow, mx);
        float alpha = __expf(mrow - mnew);   // 0 on first tile (m=-inf)
        float psum = 0.f;
        #pragma unroll
        for (int j = 0; j < 16; j++) {
            s[j] = __expf(s[j] - mnew);
            psum += s[j];
        }
        psum += __shfl_xor_sync(0xffffffffu, psum, 1);
        psum += __shfl_xor_sync(0xffffffffu, psum, 2);
        lrow = lrow * alpha + psum;
        mrow = mnew;
        #pragma unroll
        for (int i = 0; i < 16; i++) o[i] *= alpha;

        // ---- load V tile into the same smem buffer ----
        const float* Vt = Vb + (size_t)kt * 64 * HD_;
        __syncthreads();   // all warps done reading K
        #pragma unroll
        for (int i = 0; i < 4; i++) {
            int idx = tid + i * 256;
            int rr = idx >> 4;
            int cc = (idx & 15) << 2;
            *(float4*)&KVs[rr][cc] = *(const float4*)(Vt + rr * HD_ + cc);
        }
        __syncthreads();

        // ---- O += P @ V ; p value for column c lives in lane (r, c&3), slot c>>2
        #pragma unroll
        for (int c = 0; c < 64; c++) {
            float p = __shfl_sync(0xffffffffu, s[c >> 2], c & 3, 4);
            float4 v0 = *(const float4*)&KVs[c][tx8];
            float4 v1 = *(const float4*)&KVs[c][tx8 + 4];
            float4 v2 = *(const float4*)&KVs[c][32 + tx8];
            float4 v3 = *(const float4*)&KVs[c][32 + tx8 + 4];
            o[0]  = fmaf(p, v0.x, o[0]);  o[1]  = fmaf(p, v0.y, o[1]);
            o[2]  = fmaf(p, v0.z, o[2]);  o[3]  = fmaf(p, v0.w, o[3]);
            o[4]  = fmaf(p, v1.x, o[4]);  o[5]  = fmaf(p, v1.y, o[5]);
            o[6]  = fmaf(p, v1.z, o[6]);  o[7]  = fmaf(p, v1.w, o[7]);
            o[8]  = fmaf(p, v2.x, o[8]);  o[9]  = fmaf(p, v2.y, o[9]);
            o[10] = fmaf(p, v2.z, o[10]); o[11] = fmaf(p, v2.w, o[11]);
            o[12] = fmaf(p, v3.x, o[12]); o[13] = fmaf(p, v3.y, o[13]);
            o[14] = fmaf(p, v3.z, o[14]); o[15] = fmaf(p, v3.w, o[15]);
        }
    }

    // ---- epilogue: out is (B, S, H, hd) flattened to (B, S, D) ----
    float inv = 1.f / lrow;
    int b = bh >> 4;
    int h = bh & 15;
    size_t base = (((size_t)b * S_ + qt * 64 + r) * H_ + h) * HD_;
    float4 w0 = make_float4(o[0] * inv,  o[1] * inv,  o[2] * inv,  o[3] * inv);
    float4 w1 = make_float4(o[4] * inv,  o[5] * inv,  o[6] * inv,  o[7] * inv);
    float4 w2 = make_float4(o[8] * inv,  o[9] * inv,  o[10] * inv, o[11] * inv);
    float4 w3 = make_float4(o[12] * inv, o[13] * inv, o[14] * inv, o[15] * inv);
    *(float4*)&out[base + tx8]          = w0;
    *(float4*)&out[base + tx8 + 4]      = w1;
    *(float4*)&out[base + 32 + tx8]     = w2;
    *(float4*)&out[base + 32 + tx8 + 4] = w3;
}

extern "C" void kernel_launch(void* const* d_in, const int* in_sizes, int n_in,
                              void* d_out, int out_size)
{
    const float* hs = (const float*)d_in[0];   // hidden_states (2,2048,1024)
    const float* w  = (const float*)d_in[1];   // W_qkv (1024,3072)
    const float* qb = (const float*)d_in[2];   // q_bias (1024)
    const float* vb = (const float*)d_in[3];   // v_bias (1024)
    float* out = (float*)d_out;                // (2,2048,1024)

    dim3 g1(N3_ / 128, M_ / 128);   // 24 x 32
    qkv_gemm_kernel<<<g1, 256>>>(hs, w, qb, vb);

    dim3 g2(S_ / 64, B_ * H_);      // 32 x 32
    attn_kernel<<<g2, 256>>>(out);
}

// round 2
// speedup vs baseline: 1.9466x; 1.9466x over previous
#include <cuda_runtime.h>
#include <math.h>
#include <stdint.h>

#define B_  2
#define S_  2048
#define D_  1024
#define H_  16
#define HD_ 64
#define M_  (B_ * S_)    // 4096
#define N3_ (3 * D_)     // 3072

// Scratch for Q/K/V in (b*H+h, s, e) layout.
__device__ float g_Q[(size_t)M_ * D_];
__device__ float g_K[(size_t)M_ * D_];
__device__ float g_V[(size_t)M_ * D_];

// ---------------------------------------------------------------------------
// Kernel 1: fused QKV projection (fp32, unchanged; already at FMA floor).
// ---------------------------------------------------------------------------
__global__ __launch_bounds__(256) void qkv_gemm_kernel(
    const float* __restrict__ A, const float* __restrict__ W,
    const float* __restrict__ qb, const float* __restrict__ vb)
{
    __shared__ float As[8][128];
    __shared__ float Bs[8][128];

    const int tid = threadIdx.x;
    const int bm  = blockIdx.y * 128;
    const int bn  = blockIdx.x * 128;
    const int ty  = tid >> 4;
    const int tx  = tid & 15;

    const int arow = tid >> 1;
    const int acol = (tid & 1) << 2;
    const int brow = tid >> 5;
    const int bcol = (tid & 31) << 2;

    const float* Ap = A + (size_t)(bm + arow) * D_ + acol;
    const float* Wp = W + (size_t)brow * N3_ + bn + bcol;

    float acc[8][8];
    #pragma unroll
    for (int i = 0; i < 8; i++)
        #pragma unroll
        for (int j = 0; j < 8; j++) acc[i][j] = 0.f;

    for (int k0 = 0; k0 < D_; k0 += 8) {
        float4 av = *(const float4*)(Ap + k0);
        float4 wv = *(const float4*)(Wp + (size_t)k0 * N3_);
        __syncthreads();
        As[acol + 0][arow] = av.x;
        As[acol + 1][arow] = av.y;
        As[acol + 2][arow] = av.z;
        As[acol + 3][arow] = av.w;
        *(float4*)&Bs[brow][bcol] = wv;
        __syncthreads();

        #pragma unroll
        for (int k = 0; k < 8; k++) {
            float a[8], b[8];
            *(float4*)&a[0] = *(const float4*)&As[k][ty * 8];
            *(float4*)&a[4] = *(const float4*)&As[k][ty * 8 + 4];
            *(float4*)&b[0] = *(const float4*)&Bs[k][tx * 8];
            *(float4*)&b[4] = *(const float4*)&Bs[k][tx * 8 + 4];
            #pragma unroll
            for (int i = 0; i < 8; i++)
                #pragma unroll
                for (int j = 0; j < 8; j++)
                    acc[i][j] = fmaf(a[i], b[j], acc[i][j]);
        }
    }

    #pragma unroll
    for (int i = 0; i < 8; i++) {
        int mrow = bm + ty * 8 + i;
        int b = mrow >> 11;
        int s = mrow & (S_ - 1);
        #pragma unroll
        for (int j = 0; j < 8; j++) {
            int n = bn + tx * 8 + j;
            int which = n >> 10;
            int d = n & (D_ - 1);
            int h = d >> 6;
            int e = d & 63;
            size_t idx = ((size_t)(b * H_ + h) * S_ + s) * HD_ + e;
            float v = acc[i][j];
            if (which == 0)      g_Q[idx] = (v + qb[d]) * 0.125f;
            else if (which == 1) g_K[idx] = v;
            else                 g_V[idx] = v + vb[d];
        }
    }
}

// ---------------------------------------------------------------------------
// TF32 MMA helpers (m16n8k8, row.col, fp32 accumulate)
// ---------------------------------------------------------------------------
__device__ __forceinline__ uint32_t f2tf(float x) {
    uint32_t r;
    asm("cvt.rna.tf32.f32 %0, %1;" : "=r"(r) : "f"(x));
    return r;
}

__device__ __forceinline__ void mma_tf32(float c[4],
    uint32_t a0, uint32_t a1, uint32_t a2, uint32_t a3,
    uint32_t b0, uint32_t b1)
{
    asm volatile(
        "mma.sync.aligned.m16n8k8.row.col.f32.tf32.tf32.f32 "
        "{%0,%1,%2,%3}, {%4,%5,%6,%7}, {%8,%9}, {%0,%1,%2,%3};"
        : "+f"(c[0]), "+f"(c[1]), "+f"(c[2]), "+f"(c[3])
        : "r"(a0), "r"(a1), "r"(a2), "r"(a3), "r"(b0), "r"(b1));
}

// ---------------------------------------------------------------------------
// Kernel 2: flash attention with TF32 tensor cores.
// Block = 256 threads (8 warps), each warp owns 16 query rows (Br=128).
// Bc = 64 keys per tile. QK^T in split-TF32 (3 MMA), PV with V split (2 MMA).
// smem pitches: Q/K/P = 68, V = 72 (bank-conflict-free fragment loads).
// ---------------------------------------------------------------------------
#define QP 68
#define KP 68
#define VP 72
#define PP 68
#define SM_Q  (128 * QP)
#define SM_K  (64 * KP)
#define SM_V  (64 * VP)
#define SM_P  (8 * 16 * PP)
#define ATTN_SMEM_FLOATS (SM_Q + SM_K + SM_V + SM_P)

__global__ __launch_bounds__(256, 2) void attn2_kernel(float* __restrict__ out)
{
    extern __shared__ float sm[];
    float* Qs = sm;                 // [128][QP]
    float* Ks = Qs + SM_Q;          // [64][KP]
    float* Vs = Ks + SM_K;          // [64][VP]
    float* Ps = Vs + SM_V;          // [8 warps][16][PP]

    const int tid  = threadIdx.x;
    const int warp = tid >> 5;
    const int lane = tid & 31;
    const int g    = lane >> 2;     // group id 0..7
    const int t    = lane & 3;      // thread-in-group 0..3
    const int bh   = blockIdx.y;    // b*16 + h
    const int qt   = blockIdx.x;    // query tile (128 rows each)

    const float* Qg = g_Q + ((size_t)bh * S_ + qt * 128) * HD_;
    const float* Kg = g_K + (size_t)bh * S_ * HD_;
    const float* Vg = g_V + (size_t)bh * S_ * HD_;

    // Load Q tile: 128x64 floats = 2048 float4, 8 per thread.
    #pragma unroll
    for (int i = 0; i < 8; i++) {
        int idx = tid + i * 256;
        int row = idx >> 4;
        int col = (idx & 15) << 2;
        *(float4*)&Qs[row * QP + col] = *(const float4*)(Qg + row * HD_ + col);
    }

    float m0 = -INFINITY, m1 = -INFINITY, l0 = 0.f, l1 = 0.f;
    float O[8][4];
    #pragma unroll
    for (int nt = 0; nt < 8; nt++)
        #pragma unroll
        for (int j = 0; j < 4; j++) O[nt][j] = 0.f;

    float* Pw = Ps + warp * 16 * PP;

    for (int kt = 0; kt < S_ / 64; kt++) {
        __syncthreads();   // Q visible (kt=0); prior PV reads done (kt>0)

        // ---- stage K and V tiles (64x64 each, 4 float4 per thread each) ----
        const float* Kt = Kg + (size_t)kt * 64 * HD_;
        const float* Vt = Vg + (size_t)kt * 64 * HD_;
        #pragma unroll
        for (int i = 0; i < 4; i++) {
            int idx = tid + i * 256;
            int row = idx >> 4;
            int col = (idx & 15) << 2;
            *(float4*)&Ks[row * KP + col] = *(const float4*)(Kt + row * HD_ + col);
            *(float4*)&Vs[row * VP + col] = *(const float4*)(Vt + row * HD_ + col);
        }
        __syncthreads();

        // ---- scores: S[16x64] = Q_tile(16x64) @ K_tile^T, split-TF32 ----
        float Sf[8][4];
        #pragma unroll
        for (int nt = 0; nt < 8; nt++)
            #pragma unroll
            for (int j = 0; j < 4; j++) Sf[nt][j] = 0.f;

        #pragma unroll
        for (int kc = 0; kc < 8; kc++) {
            int qb = (warp * 16 + g) * QP + kc * 8 + t;
            float a0f = Qs[qb];
            float a1f = Qs[qb + 8 * QP];
            float a2f = Qs[qb + 4];
            float a3f = Qs[qb + 8 * QP + 4];
            uint32_t ah0 = f2tf(a0f), ah1 = f2tf(a1f), ah2 = f2tf(a2f), ah3 = f2tf(a3f);
            uint32_t al0 = f2tf(a0f - __uint_as_float(ah0));
            uint32_t al1 = f2tf(a1f - __uint_as_float(ah1));
            uint32_t al2 = f2tf(a2f - __uint_as_float(ah2));
            uint32_t al3 = f2tf(a3f - __uint_as_float(ah3));

            #pragma unroll
            for (int nt = 0; nt < 8; nt++) {
                int kb = (nt * 8 + g) * KP + kc * 8 + t;
                float b0f = Ks[kb];
                float b1f = Ks[kb + 4];
                uint32_t bh0 = f2tf(b0f), bh1 = f2tf(b1f);
                uint32_t bl0 = f2tf(b0f - __uint_as_float(bh0));
                uint32_t bl1 = f2tf(b1f - __uint_as_float(bh1));
                mma_tf32(Sf[nt], ah0, ah1, ah2, ah3, bh0, bh1);
                mma_tf32(Sf[nt], ah0, ah1, ah2, ah3, bl0, bl1);
                mma_tf32(Sf[nt], al0, al1, al2, al3, bh0, bh1);
            }
        }

        // ---- online softmax (rows g and g+8 of this warp's band) ----
        float mx0 = -INFINITY, mx1 = -INFINITY;
        #pragma unroll
        for (int nt = 0; nt < 8; nt++) {
            mx0 = fmaxf(mx0, fmaxf(Sf[nt][0], Sf[nt][1]));
            mx1 = fmaxf(mx1, fmaxf(Sf[nt][2], Sf[nt][3]));
        }
        mx0 = fmaxf(mx0, __shfl_xor_sync(0xffffffffu, mx0, 1));
        mx0 = fmaxf(mx0, __shfl_xor_sync(0xffffffffu, mx0, 2));
        mx1 = fmaxf(mx1, __shfl_xor_sync(0xffffffffu, mx1, 1));
        mx1 = fmaxf(mx1, __shfl_xor_sync(0xffffffffu, mx1, 2));

        float mn0 = fmaxf(m0, mx0);
        float mn1 = fmaxf(m1, mx1);
        float al0 = __expf(m0 - mn0);   // 0 on first tile
        float al1 = __expf(m1 - mn1);

        float ls0 = 0.f, ls1 = 0.f;
        #pragma unroll
        for (int nt = 0; nt < 8; nt++) {
            float p0 = __expf(Sf[nt][0] - mn0);
            float p1 = __expf(Sf[nt][1] - mn0);
            float p2 = __expf(Sf[nt][2] - mn1);
            float p3 = __expf(Sf[nt][3] - mn1);
            ls0 += p0 + p1;
            ls1 += p2 + p3;
            int pc = nt * 8 + 2 * t;
            *(float2*)&Pw[g * PP + pc]       = make_float2(p0, p1);
            *(float2*)&Pw[(g + 8) * PP + pc] = make_float2(p2, p3);
        }
        ls0 += __shfl_xor_sync(0xffffffffu, ls0, 1);
        ls0 += __shfl_xor_sync(0xffffffffu, ls0, 2);
        ls1 += __shfl_xor_sync(0xffffffffu, ls1, 1);
        ls1 += __shfl_xor_sync(0xffffffffu, ls1, 2);

        l0 = l0 * al0 + ls0;  m0 = mn0;
        l1 = l1 * al1 + ls1;  m1 = mn1;

        #pragma unroll
        for (int nt = 0; nt < 8; nt++) {
            O[nt][0] *= al0;  O[nt][1] *= al0;
            O[nt][2] *= al1;  O[nt][3] *= al1;
        }
        __syncwarp();

        // ---- O += P @ V  (P single-pass tf32, V split) ----
        #pragma unroll
        for (int kc = 0; kc < 8; kc++) {
            int pb = g * PP + kc * 8 + t;
            uint32_t a0 = f2tf(Pw[pb]);
            uint32_t a1 = f2tf(Pw[pb + 8 * PP]);
            uint32_t a2 = f2tf(Pw[pb + 4]);
            uint32_t a3 = f2tf(Pw[pb + 8 * PP + 4]);

            #pragma unroll
            for (int nt = 0; nt < 8; nt++) {
                int vb = (kc * 8 + t) * VP + nt * 8 + g;
                float b0f = Vs[vb];
                float b1f = Vs[vb + 4 * VP];
                uint32_t bh0 = f2tf(b0f), bh1 = f2tf(b1f);
                uint32_t bl0 = f2tf(b0f - __uint_as_float(bh0));
                uint32_t bl1 = f2tf(b1f - __uint_as_float(bh1));
                mma_tf32(O[nt], a0, a1, a2, a3, bh0, bh1);
                mma_tf32(O[nt], a0, a1, a2, a3, bl0, bl1);
            }
        }
        __syncwarp();   // P reads done before next tile overwrites
    }

    // ---- epilogue: out is (B, S, H, hd) flattened ----
    float inv0 = 1.f / l0;
    float inv1 = 1.f / l1;
    int b = bh >> 4;
    int h = bh & 15;
    int srow = qt * 128 + warp * 16 + g;
    size_t base0 = ((size_t)(b * S_ + srow) * H_ + h) * HD_;
    size_t base1 = base0 + (size_t)8 * H_ * HD_;   // row g+8

    #pragma unroll
    for (int nt = 0; nt < 8; nt++) {
        int col = nt * 8 + 2 * t;
        *(float2*)&out[base0 + col] = make_float2(O[nt][0] * inv0, O[nt][1] * inv0);
        *(float2*)&out[base1 + col] = make_float2(O[nt][2] * inv1, O[nt][3] * inv1);
    }
}

extern "C" void kernel_launch(void* const* d_in, const int* in_sizes, int n_in,
                              void* d_out, int out_size)
{
    const float* hs = (const float*)d_in[0];
    const float* w  = (const float*)d_in[1];
    const float* qb = (const float*)d_in[2];
    const float* vb = (const float*)d_in[3];
    float* out = (float*)d_out;

    dim3 g1(N3_ / 128, M_ / 128);
    qkv_gemm_kernel<<<g1, 256>>>(hs, w, qb, vb);

    const int smem_bytes = ATTN_SMEM_FLOATS * sizeof(float);   // 105472
    cudaFuncSetAttribute(attn2_kernel,
                         cudaFuncAttributeMaxDynamicSharedMemorySize, smem_bytes);
    dim3 g2(S_ / 128, B_ * H_);     // 16 x 32
    attn2_kernel<<<g2, 256, smem_bytes>>>(out);
}

// round 3
// speedup vs baseline: 1.9475x; 1.0004x over previous
#include <cuda_runtime.h>
#include <math.h>
#include <stdint.h>

#define B_  2
#define S_  2048
#define D_  1024
#define H_  16
#define HD_ 64
#define M_  (B_ * S_)    // 4096
#define N3_ (3 * D_)     // 3072

// Scratch for Q/K/V in (b*H+h, s, e) layout.
__device__ float g_Q[(size_t)M_ * D_];
__device__ float g_K[(size_t)M_ * D_];
__device__ float g_V[(size_t)M_ * D_];

// ---------------------------------------------------------------------------
// Kernel 1: fused QKV projection (fp32, unchanged; already at FMA floor).
// ---------------------------------------------------------------------------
__global__ __launch_bounds__(256) void qkv_gemm_kernel(
    const float* __restrict__ A, const float* __restrict__ W,
    const float* __restrict__ qb, const float* __restrict__ vb)
{
    __shared__ float As[8][128];
    __shared__ float Bs[8][128];

    const int tid = threadIdx.x;
    const int bm  = blockIdx.y * 128;
    const int bn  = blockIdx.x * 128;
    const int ty  = tid >> 4;
    const int tx  = tid & 15;

    const int arow = tid >> 1;
    const int acol = (tid & 1) << 2;
    const int brow = tid >> 5;
    const int bcol = (tid & 31) << 2;

    const float* Ap = A + (size_t)(bm + arow) * D_ + acol;
    const float* Wp = W + (size_t)brow * N3_ + bn + bcol;

    float acc[8][8];
    #pragma unroll
    for (int i = 0; i < 8; i++)
        #pragma unroll
        for (int j = 0; j < 8; j++) acc[i][j] = 0.f;

    for (int k0 = 0; k0 < D_; k0 += 8) {
        float4 av = *(const float4*)(Ap + k0);
        float4 wv = *(const float4*)(Wp + (size_t)k0 * N3_);
        __syncthreads();
        As[acol + 0][arow] = av.x;
        As[acol + 1][arow] = av.y;
        As[acol + 2][arow] = av.z;
        As[acol + 3][arow] = av.w;
        *(float4*)&Bs[brow][bcol] = wv;
        __syncthreads();

        #pragma unroll
        for (int k = 0; k < 8; k++) {
            float a[8], b[8];
            *(float4*)&a[0] = *(const float4*)&As[k][ty * 8];
            *(float4*)&a[4] = *(const float4*)&As[k][ty * 8 + 4];
            *(float4*)&b[0] = *(const float4*)&Bs[k][tx * 8];
            *(float4*)&b[4] = *(const float4*)&Bs[k][tx * 8 + 4];
            #pragma unroll
            for (int i = 0; i < 8; i++)
                #pragma unroll
                for (int j = 0; j < 8; j++)
                    acc[i][j] = fmaf(a[i], b[j], acc[i][j]);
        }
    }

    #pragma unroll
    for (int i = 0; i < 8; i++) {
        int mrow = bm + ty * 8 + i;
        int b = mrow >> 11;
        int s = mrow & (S_ - 1);
        #pragma unroll
        for (int j = 0; j < 8; j++) {
            int n = bn + tx * 8 + j;
            int which = n >> 10;
            int d = n & (D_ - 1);
            int h = d >> 6;
            int e = d & 63;
            size_t idx = ((size_t)(b * H_ + h) * S_ + s) * HD_ + e;
            float v = acc[i][j];
            if (which == 0)      g_Q[idx] = (v + qb[d]) * 0.125f;
            else if (which == 1) g_K[idx] = v;
            else                 g_V[idx] = v + vb[d];
        }
    }
}

// ---------------------------------------------------------------------------
// TF32 MMA helpers (m16n8k8, row.col, fp32 accumulate)
// ---------------------------------------------------------------------------
__device__ __forceinline__ uint32_t f2tf(float x) {
    uint32_t r;
    asm("cvt.rna.tf32.f32 %0, %1;" : "=r"(r) : "f"(x));
    return r;
}

__device__ __forceinline__ void mma_tf32(float c[4],
    uint32_t a0, uint32_t a1, uint32_t a2, uint32_t a3,
    uint32_t b0, uint32_t b1)
{
    asm volatile(
        "mma.sync.aligned.m16n8k8.row.col.f32.tf32.tf32.f32 "
        "{%0,%1,%2,%3}, {%4,%5,%6,%7}, {%8,%9}, {%0,%1,%2,%3};"
        : "+f"(c[0]), "+f"(c[1]), "+f"(c[2]), "+f"(c[3])
        : "r"(a0), "r"(a1), "r"(a2), "r"(a3), "r"(b0), "r"(b1));
}

// ---------------------------------------------------------------------------
// Kernel 2: flash attention with TF32 tensor cores.
// Block = 256 threads (8 warps), each warp owns 16 query rows (Br=128).
// Bc = 64 keys per tile. QK^T in split-TF32 (3 MMA), PV with V split (2 MMA).
// smem pitches: Q/K/P = 68, V = 72 (bank-conflict-free fragment loads).
// ---------------------------------------------------------------------------
#define QP 68
#define KP 68
#define VP 72
#define PP 68
#define SM_Q  (128 * QP)
#define SM_K  (64 * KP)
#define SM_V  (64 * VP)
#define SM_P  (8 * 16 * PP)
#define ATTN_SMEM_FLOATS (SM_Q + SM_K + SM_V + SM_P)

__global__ __launch_bounds__(256, 2) void attn2_kernel(float* __restrict__ out)
{
    extern __shared__ float sm[];
    float* Qs = sm;                 // [128][QP]
    float* Ks = Qs + SM_Q;          // [64][KP]
    float* Vs = Ks + SM_K;          // [64][VP]
    float* Ps = Vs + SM_V;          // [8 warps][16][PP]

    const int tid  = threadIdx.x;
    const int warp = tid >> 5;
    const int lane = tid & 31;
    const int g    = lane >> 2;     // group id 0..7
    const int t    = lane & 3;      // thread-in-group 0..3
    const int bh   = blockIdx.y;    // b*16 + h
    const int qt   = blockIdx.x;    // query tile (128 rows each)

    const float* Qg = g_Q + ((size_t)bh * S_ + qt * 128) * HD_;
    const float* Kg = g_K + (size_t)bh * S_ * HD_;
    const float* Vg = g_V + (size_t)bh * S_ * HD_;

    // Load Q tile: 128x64 floats = 2048 float4, 8 per thread.
    #pragma unroll
    for (int i = 0; i < 8; i++) {
        int idx = tid + i * 256;
        int row = idx >> 4;
        int col = (idx & 15) << 2;
        *(float4*)&Qs[row * QP + col] = *(const float4*)(Qg + row * HD_ + col);
    }

    float m0 = -INFINITY, m1 = -INFINITY, l0 = 0.f, l1 = 0.f;
    float O[8][4];
    #pragma unroll
    for (int nt = 0; nt < 8; nt++)
        #pragma unroll
        for (int j = 0; j < 4; j++) O[nt][j] = 0.f;

    float* Pw = Ps + warp * 16 * PP;

    for (int kt = 0; kt < S_ / 64; kt++) {
        __syncthreads();   // Q visible (kt=0); prior PV reads done (kt>0)

        // ---- stage K and V tiles (64x64 each, 4 float4 per thread each) ----
        const float* Kt = Kg + (size_t)kt * 64 * HD_;
        const float* Vt = Vg + (size_t)kt * 64 * HD_;
        #pragma unroll
        for (int i = 0; i < 4; i++) {
            int idx = tid + i * 256;
            int row = idx >> 4;
            int col = (idx & 15) << 2;
            *(float4*)&Ks[row * KP + col] = *(const float4*)(Kt + row * HD_ + col);
            *(float4*)&Vs[row * VP + col] = *(const float4*)(Vt + row * HD_ + col);
        }
        __syncthreads();

        // ---- scores: S[16x64] = Q_tile(16x64) @ K_tile^T, split-TF32 ----
        float Sf[8][4];
        #pragma unroll
        for (int nt = 0; nt < 8; nt++)
            #pragma unroll
            for (int j = 0; j < 4; j++) Sf[nt][j] = 0.f;

        #pragma unroll
        for (int kc = 0; kc < 8; kc++) {
            int qb = (warp * 16 + g) * QP + kc * 8 + t;
            float a0f = Qs[qb];
            float a1f = Qs[qb + 8 * QP];
            float a2f = Qs[qb + 4];
            float a3f = Qs[qb + 8 * QP + 4];
            uint32_t ah0 = f2tf(a0f), ah1 = f2tf(a1f), ah2 = f2tf(a2f), ah3 = f2tf(a3f);
            uint32_t al0 = f2tf(a0f - __uint_as_float(ah0));
            uint32_t al1 = f2tf(a1f - __uint_as_float(ah1));
            uint32_t al2 = f2tf(a2f - __uint_as_float(ah2));
            uint32_t al3 = f2tf(a3f - __uint_as_float(ah3));

            #pragma unroll
            for (int nt = 0; nt < 8; nt++) {
                int kb = (nt * 8 + g) * KP + kc * 8 + t;
                float b0f = Ks[kb];
                float b1f = Ks[kb + 4];
                uint32_t bh0 = f2tf(b0f), bh1 = f2tf(b1f);
                uint32_t bl0 = f2tf(b0f - __uint_as_float(bh0));
                uint32_t bl1 = f2tf(b1f - __uint_as_float(bh1));
                mma_tf32(Sf[nt], ah0, ah1, ah2, ah3, bh0, bh1);
                mma_tf32(Sf[nt], ah0, ah1, ah2, ah3, bl0, bl1);
                mma_tf32(Sf[nt], al0, al1, al2, al3, bh0, bh1);
            }
        }

        // ---- online softmax (rows g and g+8 of this warp's band) ----
        float mx0 = -INFINITY, mx1 = -INFINITY;
        #pragma unroll
        for (int nt = 0; nt < 8; nt++) {
            mx0 = fmaxf(mx0, fmaxf(Sf[nt][0], Sf[nt][1]));
            mx1 = fmaxf(mx1, fmaxf(Sf[nt][2], Sf[nt][3]));
        }
        mx0 = fmaxf(mx0, __shfl_xor_sync(0xffffffffu, mx0, 1));
        mx0 = fmaxf(mx0, __shfl_xor_sync(0xffffffffu, mx0, 2));
        mx1 = fmaxf(mx1, __shfl_xor_sync(0xffffffffu, mx1, 1));
        mx1 = fmaxf(mx1, __shfl_xor_sync(0xffffffffu, mx1, 2));

        float mn0 = fmaxf(m0, mx0);
        float mn1 = fmaxf(m1, mx1);
        float al0 = __expf(m0 - mn0);   // 0 on first tile
        float al1 = __expf(m1 - mn1);

        float ls0 = 0.f, ls1 = 0.f;
        #pragma unroll
        for (int nt = 0; nt < 8; nt++) {
            float p0 = __expf(Sf[nt][0] - mn0);
            float p1 = __expf(Sf[nt][1] - mn0);
            float p2 = __expf(Sf[nt][2] - mn1);
            float p3 = __expf(Sf[nt][3] - mn1);
            ls0 += p0 + p1;
            ls1 += p2 + p3;
            int pc = nt * 8 + 2 * t;
            *(float2*)&Pw[g * PP + pc]       = make_float2(p0, p1);
            *(float2*)&Pw[(g + 8) * PP + pc] = make_float2(p2, p3);
        }
        ls0 += __shfl_xor_sync(0xffffffffu, ls0, 1);
        ls0 += __shfl_xor_sync(0xffffffffu, ls0, 2);
        ls1 += __shfl_xor_sync(0xffffffffu, ls1, 1);
        ls1 += __shfl_xor_sync(0xffffffffu, ls1, 2);

        l0 = l0 * al0 + ls0;  m0 = mn0;
        l1 = l1 * al1 + ls1;  m1 = mn1;

        #pragma unroll
        for (int nt = 0; nt < 8; nt++) {
            O[nt][0] *= al0;  O[nt][1] *= al0;
            O[nt][2] *= al1;  O[nt][3] *= al1;
        }
        __syncwarp();

        // ---- O += P @ V  (P single-pass tf32, V split) ----
        #pragma unroll
        for (int kc = 0; kc < 8; kc++) {
            int pb = g * PP + kc * 8 + t;
            uint32_t a0 = f2tf(Pw[pb]);
            uint32_t a1 = f2tf(Pw[pb + 8 * PP]);
            uint32_t a2 = f2tf(Pw[pb + 4]);
            uint32_t a3 = f2tf(Pw[pb + 8 * PP + 4]);

            #pragma unroll
            for (int nt = 0; nt < 8; nt++) {
                int vb = (kc * 8 + t) * VP + nt * 8 + g;
                float b0f = Vs[vb];
                float b1f = Vs[vb + 4 * VP];
                uint32_t bh0 = f2tf(b0f), bh1 = f2tf(b1f);
                uint32_t bl0 = f2tf(b0f - __uint_as_float(bh0));
                uint32_t bl1 = f2tf(b1f - __uint_as_float(bh1));
                mma_tf32(O[nt], a0, a1, a2, a3, bh0, bh1);
                mma_tf32(O[nt], a0, a1, a2, a3, bl0, bl1);
            }
        }
        __syncwarp();   // P reads done before next tile overwrites
    }

    // ---- epilogue: out is (B, S, H, hd) flattened ----
    float inv0 = 1.f / l0;
    float inv1 = 1.f / l1;
    int b = bh >> 4;
    int h = bh & 15;
    int srow = qt * 128 + warp * 16 + g;
    size_t base0 = ((size_t)(b * S_ + srow) * H_ + h) * HD_;
    size_t base1 = base0 + (size_t)8 * H_ * HD_;   // row g+8

    #pragma unroll
    for (int nt = 0; nt < 8; nt++) {
        int col = nt * 8 + 2 * t;
        *(float2*)&out[base0 + col] = make_float2(O[nt][0] * inv0, O[nt][1] * inv0);
        *(float2*)&out[base1 + col] = make_float2(O[nt][2] * inv1, O[nt][3] * inv1);
    }
}

extern "C" void kernel_launch(void* const* d_in, const int* in_sizes, int n_in,
                              void* d_out, int out_size)
{
    const float* hs = (const float*)d_in[0];
    const float* w  = (const float*)d_in[1];
    const float* qb = (const float*)d_in[2];
    const float* vb = (const float*)d_in[3];
    float* out = (float*)d_out;

    dim3 g1(N3_ / 128, M_ / 128);
    qkv_gemm_kernel<<<g1, 256>>>(hs, w, qb, vb);

    const int smem_bytes = ATTN_SMEM_FLOATS * sizeof(float);   // 105472
    cudaFuncSetAttribute(attn2_kernel,
                         cudaFuncAttributeMaxDynamicSharedMemorySize, smem_bytes);
    dim3 g2(S_ / 128, B_ * H_);     // 16 x 32
    attn2_kernel<<<g2, 256, smem_bytes>>>(out);
}

// round 4
// speedup vs baseline: 2.6088x; 1.3396x over previous
#include <cuda_runtime.h>
#include <math.h>
#include <stdint.h>

#define B_  2
#define S_  2048
#define D_  1024
#define H_  16
#define HD_ 64
#define M_  (B_ * S_)    // 4096
#define N3_ (3 * D_)     // 3072

// Scratch for Q/K/V in (b*H+h, s, e) layout.
__device__ float g_Q[(size_t)M_ * D_];
__device__ float g_K[(size_t)M_ * D_];
__device__ float g_V[(size_t)M_ * D_];

// ---------------------------------------------------------------------------
// TF32 helpers
// ---------------------------------------------------------------------------
__device__ __forceinline__ uint32_t f2tf(float x) {
    uint32_t r;
    asm("cvt.rna.tf32.f32 %0, %1;" : "=r"(r) : "f"(x));
    return r;
}
__device__ __forceinline__ float tf32r(float x) {   // rounded-to-tf32 as float
    uint32_t r;
    asm("cvt.rna.tf32.f32 %0, %1;" : "=r"(r) : "f"(x));
    return __uint_as_float(r);
}
__device__ __forceinline__ void mma_tf32(float c[4],
    uint32_t a0, uint32_t a1, uint32_t a2, uint32_t a3,
    uint32_t b0, uint32_t b1)
{
    asm volatile(
        "mma.sync.aligned.m16n8k8.row.col.f32.tf32.tf32.f32 "
        "{%0,%1,%2,%3}, {%4,%5,%6,%7}, {%8,%9}, {%0,%1,%2,%3};"
        : "+f"(c[0]), "+f"(c[1]), "+f"(c[2]), "+f"(c[3])
        : "r"(a0), "r"(a1), "r"(a2), "r"(a3), "r"(b0), "r"(b1));
}

// ---------------------------------------------------------------------------
// Kernel 1: QKV projection with split-TF32 tensor cores.
// C[4096,3072] = A[4096,1024] @ W[1024,3072], 3-MMA hi/lo split (~1e-7 rel).
// BM=128, BN=128, BK=16, 256 threads, warps 4(M)x2(N), warp tile 32x64.
// A staged [m][k] pitch 20 (20 mod 32: conflict-free (g,t) frag loads).
// W staged [k][n] pitch 136 (8 mod 32: conflict-free B frag loads, no transpose).
// ---------------------------------------------------------------------------
#define GP_A 20
#define GP_W 136

__global__ __launch_bounds__(256, 2) void qkv_mma_kernel(
    const float* __restrict__ A, const float* __restrict__ W,
    const float* __restrict__ qbias, const float* __restrict__ vbias)
{
    __shared__ float Ahi[128 * GP_A], Alo[128 * GP_A];   // 2x10240 B
    __shared__ float Whi[16 * GP_W],  Wlo[16 * GP_W];    // 2x8704 B

    const int tid  = threadIdx.x;
    const int warp = tid >> 5;
    const int lane = tid & 31;
    const int g    = lane >> 2;
    const int t    = lane & 3;
    const int bm   = blockIdx.y * 128;
    const int bn   = blockIdx.x * 128;
    const int warpM = (warp >> 1) * 32;
    const int warpN = (warp & 1) * 64;

    float C[2][8][4];
    #pragma unroll
    for (int mf = 0; mf < 2; mf++)
        #pragma unroll
        for (int nf = 0; nf < 8; nf++)
            #pragma unroll
            for (int j = 0; j < 4; j++) C[mf][nf][j] = 0.f;

    // staging coordinates (2 float4 each for A and W per thread)
    int arow[2], acg[2], wkk[2], wnn[2];
    float4 pa[2], pw[2];
    #pragma unroll
    for (int i = 0; i < 2; i++) {
        int idx = tid + i * 256;
        arow[i] = idx >> 2;            // 0..127
        acg[i]  = (idx & 3) << 2;      // 0,4,8,12
        wkk[i]  = idx >> 5;            // 0..15
        wnn[i]  = (idx & 31) << 2;     // 0..124
        pa[i] = *(const float4*)(A + (size_t)(bm + arow[i]) * D_ + acg[i]);
        pw[i] = *(const float4*)(W + (size_t)wkk[i] * N3_ + bn + wnn[i]);
    }

    for (int k0 = 0; k0 < D_ / 16; k0++) {
        __syncthreads();   // previous stage's MMA reads done

        // convert + store this stage
        #pragma unroll
        for (int i = 0; i < 2; i++) {
            float4 x = pa[i];
            float4 hi = make_float4(tf32r(x.x), tf32r(x.y), tf32r(x.z), tf32r(x.w));
            float4 lo = make_float4(tf32r(x.x - hi.x), tf32r(x.y - hi.y),
                                    tf32r(x.z - hi.z), tf32r(x.w - hi.w));
            *(float4*)&Ahi[arow[i] * GP_A + acg[i]] = hi;
            *(float4*)&Alo[arow[i] * GP_A + acg[i]] = lo;

            float4 y = pw[i];
            float4 whi = make_float4(tf32r(y.x), tf32r(y.y), tf32r(y.z), tf32r(y.w));
            float4 wlo = make_float4(tf32r(y.x - whi.x), tf32r(y.y - whi.y),
                                     tf32r(y.z - whi.z), tf32r(y.w - whi.w));
            *(float4*)&Whi[wkk[i] * GP_W + wnn[i]] = whi;
            *(float4*)&Wlo[wkk[i] * GP_W + wnn[i]] = wlo;
        }
        __syncthreads();

        // prefetch next stage (overlaps the MMA phase)
        if (k0 < D_ / 16 - 1) {
            #pragma unroll
            for (int i = 0; i < 2; i++) {
                pa[i] = *(const float4*)(A + (size_t)(bm + arow[i]) * D_
                                           + (k0 + 1) * 16 + acg[i]);
                pw[i] = *(const float4*)(W + (size_t)((k0 + 1) * 16 + wkk[i]) * N3_
                                           + bn + wnn[i]);
            }
        }

        // MMA phase: 2 k8 steps
        #pragma unroll
        for (int kc = 0; kc < 2; kc++) {
            uint32_t ah[2][4], al[2][4];
            #pragma unroll
            for (int mf = 0; mf < 2; mf++) {
                int r0 = (warpM + mf * 16 + g) * GP_A + kc * 8 + t;
                ah[mf][0] = __float_as_uint(Ahi[r0]);
                ah[mf][1] = __float_as_uint(Ahi[r0 + 8 * GP_A]);
                ah[mf][2] = __float_as_uint(Ahi[r0 + 4]);
                ah[mf][3] = __float_as_uint(Ahi[r0 + 8 * GP_A + 4]);
                al[mf][0] = __float_as_uint(Alo[r0]);
                al[mf][1] = __float_as_uint(Alo[r0 + 8 * GP_A]);
                al[mf][2] = __float_as_uint(Alo[r0 + 4]);
                al[mf][3] = __float_as_uint(Alo[r0 + 8 * GP_A + 4]);
            }
            #pragma unroll
            for (int nf = 0; nf < 8; nf++) {
                int n  = warpN + nf * 8 + g;
                int kb = (kc * 8 + t) * GP_W + n;
                uint32_t bh0 = __float_as_uint(Whi[kb]);
                uint32_t bh1 = __float_as_uint(Whi[kb + 4 * GP_W]);
                uint32_t bl0 = __float_as_uint(Wlo[kb]);
                uint32_t bl1 = __float_as_uint(Wlo[kb + 4 * GP_W]);
                #pragma unroll
                for (int mf = 0; mf < 2; mf++) {
                    mma_tf32(C[mf][nf], ah[mf][0], ah[mf][1], ah[mf][2], ah[mf][3], bh0, bh1);
                    mma_tf32(C[mf][nf], ah[mf][0], ah[mf][1], ah[mf][2], ah[mf][3], bl0, bl1);
                    mma_tf32(C[mf][nf], al[mf][0], al[mf][1], al[mf][2], al[mf][3], bh0, bh1);
                }
            }
        }
    }

    // Epilogue: scatter into (b*H+h, s, e) layout with bias/scale.
    const int which = bn >> 10;   // 0=q 1=k 2=v (uniform per block)
    #pragma unroll
    for (int mf = 0; mf < 2; mf++) {
        int mrow = bm + warpM + mf * 16 + g;
        int b = mrow >> 11;
        int s = mrow & (S_ - 1);
        #pragma unroll
        for (int nf = 0; nf < 8; nf++) {
            int ncol = bn + warpN + nf * 8 + 2 * t;
            int d = ncol & (D_ - 1);
            int h = d >> 6;
            int e = d & 63;
            size_t i0 = ((size_t)(b * H_ + h) * S_ + s) * HD_ + e;
            size_t i1 = i0 + 8 * HD_;   // row s+8
            float c0 = C[mf][nf][0], c1 = C[mf][nf][1];
            float c2 = C[mf][nf][2], c3 = C[mf][nf][3];
            if (which == 0) {
                float b0 = qbias[d], b1 = qbias[d + 1];
                *(float2*)&g_Q[i0] = make_float2((c0 + b0) * 0.125f, (c1 + b1) * 0.125f);
                *(float2*)&g_Q[i1] = make_float2((c2 + b0) * 0.125f, (c3 + b1) * 0.125f);
            } else if (which == 1) {
                *(float2*)&g_K[i0] = make_float2(c0, c1);
                *(float2*)&g_K[i1] = make_float2(c2, c3);
            } else {
                float b0 = vbias[d], b1 = vbias[d + 1];
                *(float2*)&g_V[i0] = make_float2(c0 + b0, c1 + b1);
                *(float2*)&g_V[i1] = make_float2(c2 + b0, c3 + b1);
            }
        }
    }
}

// ---------------------------------------------------------------------------
// Kernel 2: flash attention, TF32 MMA, pre-converted hi/lo K/V in smem,
// P relayout via warp shuffles (no P smem).
// Block = 256 threads (8 warps), Br=128 (16 q rows/warp), Bc=64.
// smem: Qs raw [128][68]; Khi/Klo [64][68]; Vhi/Vlo [64][72]. 104 KB -> 2 blk/SM.
// ---------------------------------------------------------------------------
#define QP 68
#define KP 68
#define VP 72
#define SM_Q  (128 * QP)
#define SM_K  (64 * KP)
#define SM_V  (64 * VP)
#define ATTN_SMEM_FLOATS (SM_Q + 2 * SM_K + 2 * SM_V)

__global__ __launch_bounds__(256, 2) void attn3_kernel(float* __restrict__ out)
{
    extern __shared__ float sm[];
    float* Qs  = sm;                   // [128][QP] raw fp32
    float* Khi = Qs + SM_Q;            // [64][KP] tf32-rounded
    float* Klo = Khi + SM_K;
    float* Vhi = Klo + SM_K;           // [64][VP]
    float* Vlo = Vhi + SM_V;

    const int tid  = threadIdx.x;
    const int warp = tid >> 5;
    const int lane = tid & 31;
    const int g    = lane >> 2;
    const int t    = lane & 3;
    const int bh   = blockIdx.y;
    const int qt   = blockIdx.x;

    const float* Qg = g_Q + ((size_t)bh * S_ + qt * 128) * HD_;
    const float* Kg = g_K + (size_t)bh * S_ * HD_;
    const float* Vg = g_V + (size_t)bh * S_ * HD_;

    // Load Q tile (128x64): 8 float4 per thread
    #pragma unroll
    for (int i = 0; i < 8; i++) {
        int idx = tid + i * 256;
        int row = idx >> 4;
        int col = (idx & 15) << 2;
        *(float4*)&Qs[row * QP + col] = *(const float4*)(Qg + row * HD_ + col);
    }

    float m0 = -INFINITY, m1 = -INFINITY, l0 = 0.f, l1 = 0.f;
    float O[8][4];
    #pragma unroll
    for (int nt = 0; nt < 8; nt++)
        #pragma unroll
        for (int j = 0; j < 4; j++) O[nt][j] = 0.f;

    for (int kt = 0; kt < S_ / 64; kt++) {
        __syncthreads();   // Q visible (kt=0); prior MMA reads done (kt>0)

        // ---- stage K/V tiles, converting to hi/lo tf32 once per block ----
        const float* Kt = Kg + (size_t)kt * 64 * HD_;
        const float* Vt = Vg + (size_t)kt * 64 * HD_;
        #pragma unroll
        for (int i = 0; i < 4; i++) {
            int idx = tid + i * 256;
            int row = idx >> 4;
            int col = (idx & 15) << 2;
            float4 kx = *(const float4*)(Kt + row * HD_ + col);
            float4 vx = *(const float4*)(Vt + row * HD_ + col);
            float4 khi = make_float4(tf32r(kx.x), tf32r(kx.y), tf32r(kx.z), tf32r(kx.w));
            float4 klo = make_float4(tf32r(kx.x - khi.x), tf32r(kx.y - khi.y),
                                     tf32r(kx.z - khi.z), tf32r(kx.w - khi.w));
            float4 vhi = make_float4(tf32r(vx.x), tf32r(vx.y), tf32r(vx.z), tf32r(vx.w));
            float4 vlo = make_float4(tf32r(vx.x - vhi.x), tf32r(vx.y - vhi.y),
                                     tf32r(vx.z - vhi.z), tf32r(vx.w - vhi.w));
            *(float4*)&Khi[row * KP + col] = khi;
            *(float4*)&Klo[row * KP + col] = klo;
            *(float4*)&Vhi[row * VP + col] = vhi;
            *(float4*)&Vlo[row * VP + col] = vlo;
        }
        __syncthreads();

        // ---- scores: S[16x64] = Q(16x64) @ K^T, split-TF32 (3 MMA) ----
        float Sf[8][4];
        #pragma unroll
        for (int nt = 0; nt < 8; nt++)
            #pragma unroll
            for (int j = 0; j < 4; j++) Sf[nt][j] = 0.f;

        #pragma unroll
        for (int kc = 0; kc < 8; kc++) {
            int qi = (warp * 16 + g) * QP + kc * 8 + t;
            float a0f = Qs[qi];
            float a1f = Qs[qi + 8 * QP];
            float a2f = Qs[qi + 4];
            float a3f = Qs[qi + 8 * QP + 4];
            uint32_t ah0 = f2tf(a0f), ah1 = f2tf(a1f), ah2 = f2tf(a2f), ah3 = f2tf(a3f);
            uint32_t al0 = f2tf(a0f - __uint_as_float(ah0));
            uint32_t al1 = f2tf(a1f - __uint_as_float(ah1));
            uint32_t al2 = f2tf(a2f - __uint_as_float(ah2));
            uint32_t al3 = f2tf(a3f - __uint_as_float(ah3));

            #pragma unroll
            for (int nt = 0; nt < 8; nt++) {
                int kb = (nt * 8 + g) * KP + kc * 8 + t;
                uint32_t bh0 = __float_as_uint(Khi[kb]);
                uint32_t bh1 = __float_as_uint(Khi[kb + 4]);
                uint32_t bl0 = __float_as_uint(Klo[kb]);
                uint32_t bl1 = __float_as_uint(Klo[kb + 4]);
                mma_tf32(Sf[nt], ah0, ah1, ah2, ah3, bh0, bh1);
                mma_tf32(Sf[nt], ah0, ah1, ah2, ah3, bl0, bl1);
                mma_tf32(Sf[nt], al0, al1, al2, al3, bh0, bh1);
            }
        }

        // ---- online softmax (rows g and g+8) ----
        float mx0 = -INFINITY, mx1 = -INFINITY;
        #pragma unroll
        for (int nt = 0; nt < 8; nt++) {
            mx0 = fmaxf(mx0, fmaxf(Sf[nt][0], Sf[nt][1]));
            mx1 = fmaxf(mx1, fmaxf(Sf[nt][2], Sf[nt][3]));
        }
        mx0 = fmaxf(mx0, __shfl_xor_sync(0xffffffffu, mx0, 1));
        mx0 = fmaxf(mx0, __shfl_xor_sync(0xffffffffu, mx0, 2));
        mx1 = fmaxf(mx1, __shfl_xor_sync(0xffffffffu, mx1, 1));
        mx1 = fmaxf(mx1, __shfl_xor_sync(0xffffffffu, mx1, 2));

        float mn0 = fmaxf(m0, mx0);
        float mn1 = fmaxf(m1, mx1);
        float alp0 = __expf(m0 - mn0);
        float alp1 = __expf(m1 - mn1);

        float ls0 = 0.f, ls1 = 0.f;
        #pragma unroll
        for (int nt = 0; nt < 8; nt++) {
            Sf[nt][0] = __expf(Sf[nt][0] - mn0);
            Sf[nt][1] = __expf(Sf[nt][1] - mn0);
            Sf[nt][2] = __expf(Sf[nt][2] - mn1);
            Sf[nt][3] = __expf(Sf[nt][3] - mn1);
            ls0 += Sf[nt][0] + Sf[nt][1];
            ls1 += Sf[nt][2] + Sf[nt][3];
        }
        ls0 += __shfl_xor_sync(0xffffffffu, ls0, 1);
        ls0 += __shfl_xor_sync(0xffffffffu, ls0, 2);
        ls1 += __shfl_xor_sync(0xffffffffu, ls1, 1);
        ls1 += __shfl_xor_sync(0xffffffffu, ls1, 2);

        l0 = l0 * alp0 + ls0;  m0 = mn0;
        l1 = l1 * alp1 + ls1;  m1 = mn1;

        #pragma unroll
        for (int nt = 0; nt < 8; nt++) {
            O[nt][0] *= alp0;  O[nt][1] *= alp0;
            O[nt][2] *= alp1;  O[nt][3] *= alp1;
        }

        // ---- O += P @ V  (P single-pass tf32 via shuffles, V split) ----
        const int src0 = (lane & ~3) + (t >> 1);   // owner of col t within quad
        const int src2 = src0 + 2;                 // owner of col t+4
        const bool odd = (t & 1);

        #pragma unroll
        for (int kc = 0; kc < 8; kc++) {
            // P A-frag: a0=P[g][8kc+t], a1=P[g+8][8kc+t], a2=P[g][8kc+t+4], a3=P[g+8][8kc+t+4]
            float e0 = __shfl_sync(0xffffffffu, Sf[kc][0], src0);
            float e1 = __shfl_sync(0xffffffffu, Sf[kc][1], src0);
            float f0 = __shfl_sync(0xffffffffu, Sf[kc][0], src2);
            float f1 = __shfl_sync(0xffffffffu, Sf[kc][1], src2);
            float h0 = __shfl_sync(0xffffffffu, Sf[kc][2], src0);
            float h1 = __shfl_sync(0xffffffffu, Sf[kc][3], src0);
            float i0 = __shfl_sync(0xffffffffu, Sf[kc][2], src2);
            float i1 = __shfl_sync(0xffffffffu, Sf[kc][3], src2);
            uint32_t a0 = f2tf(odd ? e1 : e0);
            uint32_t a1 = f2tf(odd ? h1 : h0);
            uint32_t a2 = f2tf(odd ? f1 : f0);
            uint32_t a3 = f2tf(odd ? i1 : i0);

            #pragma unroll
            for (int nt = 0; nt < 8; nt++) {
                int vi = (kc * 8 + t) * VP + nt * 8 + g;
                uint32_t bh0 = __float_as_uint(Vhi[vi]);
                uint32_t bh1 = __float_as_uint(Vhi[vi + 4 * VP]);
                uint32_t bl0 = __float_as_uint(Vlo[vi]);
                uint32_t bl1 = __float_as_uint(Vlo[vi + 4 * VP]);
                mma_tf32(O[nt], a0, a1, a2, a3, bh0, bh1);
                mma_tf32(O[nt], a0, a1, a2, a3, bl0, bl1);
            }
        }
    }

    // ---- epilogue: out is (B, S, H, hd) flattened ----
    float inv0 = 1.f / l0;
    float inv1 = 1.f / l1;
    int b = bh >> 4;
    int h = bh & 15;
    int srow = qt * 128 + warp * 16 + g;
    size_t base0 = ((size_t)(b * S_ + srow) * H_ + h) * HD_;
    size_t base1 = base0 + (size_t)8 * H_ * HD_;

    #pragma unroll
    for (int nt = 0; nt < 8; nt++) {
        int col = nt * 8 + 2 * t;
        *(float2*)&out[base0 + col] = make_float2(O[nt][0] * inv0, O[nt][1] * inv0);
        *(float2*)&out[base1 + col] = make_float2(O[nt][2] * inv1, O[nt][3] * inv1);
    }
}

extern "C" void kernel_launch(void* const* d_in, const int* in_sizes, int n_in,
                              void* d_out, int out_size)
{
    const float* hs = (const float*)d_in[0];
    const float* w  = (const float*)d_in[1];
    const float* qb = (const float*)d_in[2];
    const float* vb = (const float*)d_in[3];
    float* out = (float*)d_out;

    dim3 g1(N3_ / 128, M_ / 128);   // 24 x 32
    qkv_mma_kernel<<<g1, 256>>>(hs, w, qb, vb);

    const int smem_bytes = ATTN_SMEM_FLOATS * sizeof(float);   // 106496
    cudaFuncSetAttribute(attn3_kernel,
                         cudaFuncAttributeMaxDynamicSharedMemorySize, smem_bytes);
    dim3 g2(S_ / 128, B_ * H_);     // 16 x 32
    attn3_kernel<<<g2, 256, smem_bytes>>>(out);
}

// round 5
// speedup vs baseline: 2.8855x; 1.1060x over previous
#include <cuda_runtime.h>
#include <math.h>
#include <stdint.h>

#define B_  2
#define S_  2048
#define D_  1024
#define H_  16
#define HD_ 64
#define M_  (B_ * S_)    // 4096
#define N3_ (3 * D_)     // 3072

// Scratch for Q/K/V in (b*H+h, s, e) layout.
__device__ float g_Q[(size_t)M_ * D_];
__device__ float g_K[(size_t)M_ * D_];
__device__ float g_V[(size_t)M_ * D_];

// ---------------------------------------------------------------------------
// TF32 helpers
// ---------------------------------------------------------------------------
__device__ __forceinline__ uint32_t f2tf(float x) {
    uint32_t r;
    asm("cvt.rna.tf32.f32 %0, %1;" : "=r"(r) : "f"(x));
    return r;
}
__device__ __forceinline__ float tf32r(float x) {
    uint32_t r;
    asm("cvt.rna.tf32.f32 %0, %1;" : "=r"(r) : "f"(x));
    return __uint_as_float(r);
}
__device__ __forceinline__ void mma_tf32(float c[4],
    uint32_t a0, uint32_t a1, uint32_t a2, uint32_t a3,
    uint32_t b0, uint32_t b1)
{
    asm volatile(
        "mma.sync.aligned.m16n8k8.row.col.f32.tf32.tf32.f32 "
        "{%0,%1,%2,%3}, {%4,%5,%6,%7}, {%8,%9}, {%0,%1,%2,%3};"
        : "+f"(c[0]), "+f"(c[1]), "+f"(c[2]), "+f"(c[3])
        : "r"(a0), "r"(a1), "r"(a2), "r"(a3), "r"(b0), "r"(b1));
}

// ---------------------------------------------------------------------------
// Kernel 1: QKV projection with split-TF32 tensor cores (unchanged).
// ---------------------------------------------------------------------------
#define GP_A 20
#define GP_W 136

__global__ __launch_bounds__(256, 2) void qkv_mma_kernel(
    const float* __restrict__ A, const float* __restrict__ W,
    const float* __restrict__ qbias, const float* __restrict__ vbias)
{
    __shared__ float Ahi[128 * GP_A], Alo[128 * GP_A];
    __shared__ float Whi[16 * GP_W],  Wlo[16 * GP_W];

    const int tid  = threadIdx.x;
    const int warp = tid >> 5;
    const int lane = tid & 31;
    const int g    = lane >> 2;
    const int t    = lane & 3;
    const int bm   = blockIdx.y * 128;
    const int bn   = blockIdx.x * 128;
    const int warpM = (warp >> 1) * 32;
    const int warpN = (warp & 1) * 64;

    float C[2][8][4];
    #pragma unroll
    for (int mf = 0; mf < 2; mf++)
        #pragma unroll
        for (int nf = 0; nf < 8; nf++)
            #pragma unroll
            for (int j = 0; j < 4; j++) C[mf][nf][j] = 0.f;

    int arow[2], acg[2], wkk[2], wnn[2];
    float4 pa[2], pw[2];
    #pragma unroll
    for (int i = 0; i < 2; i++) {
        int idx = tid + i * 256;
        arow[i] = idx >> 2;
        acg[i]  = (idx & 3) << 2;
        wkk[i]  = idx >> 5;
        wnn[i]  = (idx & 31) << 2;
        pa[i] = *(const float4*)(A + (size_t)(bm + arow[i]) * D_ + acg[i]);
        pw[i] = *(const float4*)(W + (size_t)wkk[i] * N3_ + bn + wnn[i]);
    }

    for (int k0 = 0; k0 < D_ / 16; k0++) {
        __syncthreads();

        #pragma unroll
        for (int i = 0; i < 2; i++) {
            float4 x = pa[i];
            float4 hi = make_float4(tf32r(x.x), tf32r(x.y), tf32r(x.z), tf32r(x.w));
            float4 lo = make_float4(tf32r(x.x - hi.x), tf32r(x.y - hi.y),
                                    tf32r(x.z - hi.z), tf32r(x.w - hi.w));
            *(float4*)&Ahi[arow[i] * GP_A + acg[i]] = hi;
            *(float4*)&Alo[arow[i] * GP_A + acg[i]] = lo;

            float4 y = pw[i];
            float4 whi = make_float4(tf32r(y.x), tf32r(y.y), tf32r(y.z), tf32r(y.w));
            float4 wlo = make_float4(tf32r(y.x - whi.x), tf32r(y.y - whi.y),
                                     tf32r(y.z - whi.z), tf32r(y.w - whi.w));
            *(float4*)&Whi[wkk[i] * GP_W + wnn[i]] = whi;
            *(float4*)&Wlo[wkk[i] * GP_W + wnn[i]] = wlo;
        }
        __syncthreads();

        if (k0 < D_ / 16 - 1) {
            #pragma unroll
            for (int i = 0; i < 2; i++) {
                pa[i] = *(const float4*)(A + (size_t)(bm + arow[i]) * D_
                                           + (k0 + 1) * 16 + acg[i]);
                pw[i] = *(const float4*)(W + (size_t)((k0 + 1) * 16 + wkk[i]) * N3_
                                           + bn + wnn[i]);
            }
        }

        #pragma unroll
        for (int kc = 0; kc < 2; kc++) {
            uint32_t ah[2][4], al[2][4];
            #pragma unroll
            for (int mf = 0; mf < 2; mf++) {
                int r0 = (warpM + mf * 16 + g) * GP_A + kc * 8 + t;
                ah[mf][0] = __float_as_uint(Ahi[r0]);
                ah[mf][1] = __float_as_uint(Ahi[r0 + 8 * GP_A]);
                ah[mf][2] = __float_as_uint(Ahi[r0 + 4]);
                ah[mf][3] = __float_as_uint(Ahi[r0 + 8 * GP_A + 4]);
                al[mf][0] = __float_as_uint(Alo[r0]);
                al[mf][1] = __float_as_uint(Alo[r0 + 8 * GP_A]);
                al[mf][2] = __float_as_uint(Alo[r0 + 4]);
                al[mf][3] = __float_as_uint(Alo[r0 + 8 * GP_A + 4]);
            }
            #pragma unroll
            for (int nf = 0; nf < 8; nf++) {
                int n  = warpN + nf * 8 + g;
                int kb = (kc * 8 + t) * GP_W + n;
                uint32_t bh0 = __float_as_uint(Whi[kb]);
                uint32_t bh1 = __float_as_uint(Whi[kb + 4 * GP_W]);
                uint32_t bl0 = __float_as_uint(Wlo[kb]);
                uint32_t bl1 = __float_as_uint(Wlo[kb + 4 * GP_W]);
                #pragma unroll
                for (int mf = 0; mf < 2; mf++) {
                    mma_tf32(C[mf][nf], ah[mf][0], ah[mf][1], ah[mf][2], ah[mf][3], bh0, bh1);
                    mma_tf32(C[mf][nf], ah[mf][0], ah[mf][1], ah[mf][2], ah[mf][3], bl0, bl1);
                    mma_tf32(C[mf][nf], al[mf][0], al[mf][1], al[mf][2], al[mf][3], bh0, bh1);
                }
            }
        }
    }

    const int which = bn >> 10;
    #pragma unroll
    for (int mf = 0; mf < 2; mf++) {
        int mrow = bm + warpM + mf * 16 + g;
        int b = mrow >> 11;
        int s = mrow & (S_ - 1);
        #pragma unroll
        for (int nf = 0; nf < 8; nf++) {
            int ncol = bn + warpN + nf * 8 + 2 * t;
            int d = ncol & (D_ - 1);
            int h = d >> 6;
            int e = d & 63;
            size_t i0 = ((size_t)(b * H_ + h) * S_ + s) * HD_ + e;
            size_t i1 = i0 + 8 * HD_;
            float c0 = C[mf][nf][0], c1 = C[mf][nf][1];
            float c2 = C[mf][nf][2], c3 = C[mf][nf][3];
            if (which == 0) {
                float b0 = qbias[d], b1 = qbias[d + 1];
                *(float2*)&g_Q[i0] = make_float2((c0 + b0) * 0.125f, (c1 + b1) * 0.125f);
                *(float2*)&g_Q[i1] = make_float2((c2 + b0) * 0.125f, (c3 + b1) * 0.125f);
            } else if (which == 1) {
                *(float2*)&g_K[i0] = make_float2(c0, c1);
                *(float2*)&g_K[i1] = make_float2(c2, c3);
            } else {
                float b0 = vbias[d], b1 = vbias[d + 1];
                *(float2*)&g_V[i0] = make_float2(c0 + b0, c1 + b1);
                *(float2*)&g_V[i1] = make_float2(c2 + b0, c3 + b1);
            }
        }
    }
}

// ---------------------------------------------------------------------------
// Kernel 2: flash attention, TF32 MMA.
// Block = 128 threads (4 warps), warp tile M=32 (2 m-frags), Br=128, Bc=64.
// K/V smem bytes per FLOP halved vs 8-warp version (4 readers not 8);
// V is single-pass tf32 (PV = 1 MMA) — K stays split (3 MMA) for score accuracy.
// smem: Qs raw [128][68]; Khi/Klo [64][68]; Vhi [64][72] = 88 KB -> 2 blk/SM.
// ---------------------------------------------------------------------------
#define QP 68
#define KP 68
#define VP 72
#define SM_Q  (128 * QP)
#define SM_K  (64 * KP)
#define SM_V  (64 * VP)
#define ATTN_SMEM_FLOATS (SM_Q + 2 * SM_K + SM_V)

__global__ __launch_bounds__(128, 2) void attn4_kernel(float* __restrict__ out)
{
    extern __shared__ float sm[];
    float* Qs  = sm;                   // [128][QP] raw fp32
    float* Khi = Qs + SM_Q;            // [64][KP]
    float* Klo = Khi + SM_K;
    float* Vhi = Klo + SM_K;           // [64][VP]

    const int tid  = threadIdx.x;
    const int warp = tid >> 5;
    const int lane = tid & 31;
    const int g    = lane >> 2;
    const int t    = lane & 3;
    const int wm   = warp * 32;        // warp's 32-row band
    const int bh   = blockIdx.y;
    const int qt   = blockIdx.x;

    const float* Qg = g_Q + ((size_t)bh * S_ + qt * 128) * HD_;
    const float* Kg = g_K + (size_t)bh * S_ * HD_;
    const float* Vg = g_V + (size_t)bh * S_ * HD_;

    // Load Q tile (128x64): 16 float4 per thread
    #pragma unroll
    for (int i = 0; i < 16; i++) {
        int idx = tid + i * 128;
        int row = idx >> 4;
        int col = (idx & 15) << 2;
        *(float4*)&Qs[row * QP + col] = *(const float4*)(Qg + row * HD_ + col);
    }

    float m[2][2], l[2][2];
    #pragma unroll
    for (int mf = 0; mf < 2; mf++) {
        m[mf][0] = -INFINITY; m[mf][1] = -INFINITY;
        l[mf][0] = 0.f;       l[mf][1] = 0.f;
    }
    float O[2][8][4];
    #pragma unroll
    for (int mf = 0; mf < 2; mf++)
        #pragma unroll
        for (int nt = 0; nt < 8; nt++)
            #pragma unroll
            for (int j = 0; j < 4; j++) O[mf][nt][j] = 0.f;

    for (int kt = 0; kt < S_ / 64; kt++) {
        __syncthreads();

        // ---- stage K (hi/lo) and V (hi only): 8 float4 per thread each ----
        const float* Kt = Kg + (size_t)kt * 64 * HD_;
        const float* Vt = Vg + (size_t)kt * 64 * HD_;
        #pragma unroll
        for (int i = 0; i < 8; i++) {
            int idx = tid + i * 128;
            int row = idx >> 4;
            int col = (idx & 15) << 2;
            float4 kx = *(const float4*)(Kt + row * HD_ + col);
            float4 vx = *(const float4*)(Vt + row * HD_ + col);
            float4 khi = make_float4(tf32r(kx.x), tf32r(kx.y), tf32r(kx.z), tf32r(kx.w));
            float4 klo = make_float4(tf32r(kx.x - khi.x), tf32r(kx.y - khi.y),
                                     tf32r(kx.z - khi.z), tf32r(kx.w - khi.w));
            float4 vhi = make_float4(tf32r(vx.x), tf32r(vx.y), tf32r(vx.z), tf32r(vx.w));
            *(float4*)&Khi[row * KP + col] = khi;
            *(float4*)&Klo[row * KP + col] = klo;
            *(float4*)&Vhi[row * VP + col] = vhi;
        }
        __syncthreads();

        // ---- scores: S[32x64] = Q(32x64) @ K^T, split-TF32 (3 MMA) ----
        float Sf[2][8][4];
        #pragma unroll
        for (int mf = 0; mf < 2; mf++)
            #pragma unroll
            for (int nt = 0; nt < 8; nt++)
                #pragma unroll
                for (int j = 0; j < 4; j++) Sf[mf][nt][j] = 0.f;

        #pragma unroll
        for (int kc = 0; kc < 8; kc++) {
            uint32_t ah[2][4], al[2][4];
            #pragma unroll
            for (int mf = 0; mf < 2; mf++) {
                int qi = (wm + mf * 16 + g) * QP + kc * 8 + t;
                float a0f = Qs[qi];
                float a1f = Qs[qi + 8 * QP];
                float a2f = Qs[qi + 4];
                float a3f = Qs[qi + 8 * QP + 4];
                ah[mf][0] = f2tf(a0f); ah[mf][1] = f2tf(a1f);
                ah[mf][2] = f2tf(a2f); ah[mf][3] = f2tf(a3f);
                al[mf][0] = f2tf(a0f - __uint_as_float(ah[mf][0]));
                al[mf][1] = f2tf(a1f - __uint_as_float(ah[mf][1]));
                al[mf][2] = f2tf(a2f - __uint_as_float(ah[mf][2]));
                al[mf][3] = f2tf(a3f - __uint_as_float(ah[mf][3]));
            }
            #pragma unroll
            for (int nt = 0; nt < 8; nt++) {
                int kb = (nt * 8 + g) * KP + kc * 8 + t;
                uint32_t bh0 = __float_as_uint(Khi[kb]);
                uint32_t bh1 = __float_as_uint(Khi[kb + 4]);
                uint32_t bl0 = __float_as_uint(Klo[kb]);
                uint32_t bl1 = __float_as_uint(Klo[kb + 4]);
                #pragma unroll
                for (int mf = 0; mf < 2; mf++) {
                    mma_tf32(Sf[mf][nt], ah[mf][0], ah[mf][1], ah[mf][2], ah[mf][3], bh0, bh1);
                    mma_tf32(Sf[mf][nt], ah[mf][0], ah[mf][1], ah[mf][2], ah[mf][3], bl0, bl1);
                    mma_tf32(Sf[mf][nt], al[mf][0], al[mf][1], al[mf][2], al[mf][3], bh0, bh1);
                }
            }
        }

        // ---- online softmax per m-frag (rows g and g+8 of each band) ----
        #pragma unroll
        for (int mf = 0; mf < 2; mf++) {
            float mx0 = -INFINITY, mx1 = -INFINITY;
            #pragma unroll
            for (int nt = 0; nt < 8; nt++) {
                mx0 = fmaxf(mx0, fmaxf(Sf[mf][nt][0], Sf[mf][nt][1]));
                mx1 = fmaxf(mx1, fmaxf(Sf[mf][nt][2], Sf[mf][nt][3]));
            }
            mx0 = fmaxf(mx0, __shfl_xor_sync(0xffffffffu, mx0, 1));
            mx0 = fmaxf(mx0, __shfl_xor_sync(0xffffffffu, mx0, 2));
            mx1 = fmaxf(mx1, __shfl_xor_sync(0xffffffffu, mx1, 1));
            mx1 = fmaxf(mx1, __shfl_xor_sync(0xffffffffu, mx1, 2));

            float mn0 = fmaxf(m[mf][0], mx0);
            float mn1 = fmaxf(m[mf][1], mx1);
            float alp0 = __expf(m[mf][0] - mn0);
            float alp1 = __expf(m[mf][1] - mn1);

            float ls0 = 0.f, ls1 = 0.f;
            #pragma unroll
            for (int nt = 0; nt < 8; nt++) {
                Sf[mf][nt][0] = __expf(Sf[mf][nt][0] - mn0);
                Sf[mf][nt][1] = __expf(Sf[mf][nt][1] - mn0);
                Sf[mf][nt][2] = __expf(Sf[mf][nt][2] - mn1);
                Sf[mf][nt][3] = __expf(Sf[mf][nt][3] - mn1);
                ls0 += Sf[mf][nt][0] + Sf[mf][nt][1];
                ls1 += Sf[mf][nt][2] + Sf[mf][nt][3];
            }
            ls0 += __shfl_xor_sync(0xffffffffu, ls0, 1);
            ls0 += __shfl_xor_sync(0xffffffffu, ls0, 2);
            ls1 += __shfl_xor_sync(0xffffffffu, ls1, 1);
            ls1 += __shfl_xor_sync(0xffffffffu, ls1, 2);

            l[mf][0] = l[mf][0] * alp0 + ls0;  m[mf][0] = mn0;
            l[mf][1] = l[mf][1] * alp1 + ls1;  m[mf][1] = mn1;

            #pragma unroll
            for (int nt = 0; nt < 8; nt++) {
                O[mf][nt][0] *= alp0;  O[mf][nt][1] *= alp0;
                O[mf][nt][2] *= alp1;  O[mf][nt][3] *= alp1;
            }
        }

        // ---- O += P @ V  (P tf32 via shuffles, V single-pass) ----
        const int src0 = (lane & ~3) + (t >> 1);
        const int src2 = src0 + 2;
        const bool odd = (t & 1);

        #pragma unroll
        for (int kc = 0; kc < 8; kc++) {
            uint32_t a[2][4];
            #pragma unroll
            for (int mf = 0; mf < 2; mf++) {
                float e0 = __shfl_sync(0xffffffffu, Sf[mf][kc][0], src0);
                float e1 = __shfl_sync(0xffffffffu, Sf[mf][kc][1], src0);
                float f0 = __shfl_sync(0xffffffffu, Sf[mf][kc][0], src2);
                float f1 = __shfl_sync(0xffffffffu, Sf[mf][kc][1], src2);
                float h0 = __shfl_sync(0xffffffffu, Sf[mf][kc][2], src0);
                float h1 = __shfl_sync(0xffffffffu, Sf[mf][kc][3], src0);
                float i0 = __shfl_sync(0xffffffffu, Sf[mf][kc][2], src2);
                float i1 = __shfl_sync(0xffffffffu, Sf[mf][kc][3], src2);
                a[mf][0] = f2tf(odd ? e1 : e0);
                a[mf][1] = f2tf(odd ? h1 : h0);
                a[mf][2] = f2tf(odd ? f1 : f0);
                a[mf][3] = f2tf(odd ? i1 : i0);
            }
            #pragma unroll
            for (int nt = 0; nt < 8; nt++) {
                int vi = (kc * 8 + t) * VP + nt * 8 + g;
                uint32_t bh0 = __float_as_uint(Vhi[vi]);
                uint32_t bh1 = __float_as_uint(Vhi[vi + 4 * VP]);
                #pragma unroll
                for (int mf = 0; mf < 2; mf++)
                    mma_tf32(O[mf][nt], a[mf][0], a[mf][1], a[mf][2], a[mf][3], bh0, bh1);
            }
        }
    }

    // ---- epilogue: out is (B, S, H, hd) flattened ----
    int b = bh >> 4;
    int h = bh & 15;
    #pragma unroll
    for (int mf = 0; mf < 2; mf++) {
        float inv0 = 1.f / l[mf][0];
        float inv1 = 1.f / l[mf][1];
        int srow = qt * 128 + wm + mf * 16 + g;
        size_t base0 = ((size_t)(b * S_ + srow) * H_ + h) * HD_;
        size_t base1 = base0 + (size_t)8 * H_ * HD_;
        #pragma unroll
        for (int nt = 0; nt < 8; nt++) {
            int col = nt * 8 + 2 * t;
            *(float2*)&out[base0 + col] =
                make_float2(O[mf][nt][0] * inv0, O[mf][nt][1] * inv0);
            *(float2*)&out[base1 + col] =
                make_float2(O[mf][nt][2] * inv1, O[mf][nt][3] * inv1);
        }
    }
}

extern "C" void kernel_launch(void* const* d_in, const int* in_sizes, int n_in,
                              void* d_out, int out_size)
{
    const float* hs = (const float*)d_in[0];
    const float* w  = (const float*)d_in[1];
    const float* qb = (const float*)d_in[2];
    const float* vb = (const float*)d_in[3];
    float* out = (float*)d_out;

    dim3 g1(N3_ / 128, M_ / 128);   // 24 x 32
    qkv_mma_kernel<<<g1, 256>>>(hs, w, qb, vb);

    const int smem_bytes = ATTN_SMEM_FLOATS * sizeof(float);   // 88064
    cudaFuncSetAttribute(attn4_kernel,
                         cudaFuncAttributeMaxDynamicSharedMemorySize, smem_bytes);
    dim3 g2(S_ / 128, B_ * H_);     // 16 x 32
    attn4_kernel<<<g2, 128, smem_bytes>>>(out);
}